// round 8
// baseline (speedup 1.0000x reference)
#include <cuda_runtime.h>
#include <cstdint>

#define N_NODES 1024
#define D 64
#define ALPHA_F 0.2f
#define MASK_VAL_F -1000000000.0f
#define LN_EPS_F 1e-5f

// ---------------- scratch (no allocations allowed) ----------------
__device__ float g_Wh[N_NODES * D];
__device__ float g_ei[N_NODES * D];   // h @ E_i + edge_b (folded)
__device__ float g_ej[N_NODES * D];   // h @ E_j
__device__ float g_qi[N_NODES * D];   // Wh @ A_i + attn_b1 (folded)
__device__ float g_kj[N_NODES * D];   // Wh @ A_j
__device__ float g_e[N_NODES * N_NODES];

// ---------------- helpers ----------------
__device__ __forceinline__ float warpReduceMax(float v) {
    #pragma unroll
    for (int o = 16; o > 0; o >>= 1) v = fmaxf(v, __shfl_xor_sync(0xffffffffu, v, o));
    return v;
}
__device__ __forceinline__ float warpReduceSum(float v) {
    #pragma unroll
    for (int o = 16; o > 0; o >>= 1) v += __shfl_xor_sync(0xffffffffu, v, o);
    return v;
}
// pack {lo, hi} floats -> bf16x2 (element0 = lo)
__device__ __forceinline__ uint32_t pack_bf16x2(float lo, float hi) {
    uint32_t r;
    asm("cvt.rn.bf16x2.f32 %0, %1, %2;" : "=r"(r) : "f"(hi), "f"(lo));
    return r;
}
__device__ __forceinline__ void mma_bf16_16x8x16(
    float& c0, float& c1, float& c2, float& c3,
    uint32_t a0, uint32_t a1, uint32_t a2, uint32_t a3,
    uint32_t b0, uint32_t b1)
{
    asm volatile(
        "mma.sync.aligned.m16n8k16.row.col.f32.bf16.bf16.f32 "
        "{%0,%1,%2,%3}, {%4,%5,%6,%7}, {%8,%9}, {%0,%1,%2,%3};"
        : "+f"(c0), "+f"(c1), "+f"(c2), "+f"(c3)
        : "r"(a0), "r"(a1), "r"(a2), "r"(a3), "r"(b0), "r"(b1));
}
__device__ __forceinline__ float leaky(float s) { return fmaxf(s, ALPHA_F * s); }

// ================================================================
// Kernel 1: per-node projections. Weights staged in SMEM.
// 128 blocks x 8 nodes, 2 nodes/thread.  (measured 7.8us config)
// ================================================================
__global__ void __launch_bounds__(256) prep_kernel(
    const float* __restrict__ h, const float* __restrict__ W,
    const float* __restrict__ attn_w1, const float* __restrict__ attn_b1,
    const float* __restrict__ edge_w, const float* __restrict__ edge_b)
{
    __shared__ float sWt[12288];          // 48KB
    __shared__ float sh[8][64];
    __shared__ float swh[8][64];
    const int t = threadIdx.x;
    const int d = t & 63;
    const int n0 = (t >> 6) * 2;
    const int nb = blockIdx.x * 8;

    #pragma unroll
    for (int x = t; x < 1024; x += 256)
        ((float4*)sWt)[x] = ((const float4*)W)[x];
    #pragma unroll
    for (int x = t; x < 2048; x += 256)
        ((float4*)(sWt + 4096))[x] = ((const float4*)edge_w)[x];
    if (t < 128)
        ((float4*)sh)[t] = ((const float4*)(h + nb * D))[t];
    __syncthreads();

    float wh0 = 0.f, wh1 = 0.f;
    float ei0 = edge_b[d], ei1 = ei0;
    float ej0 = 0.f, ej1 = 0.f;
    #pragma unroll 8
    for (int k = 0; k < D; ++k) {
        const float w  = sWt[k * 64 + d];
        const float e1 = sWt[4096 + k * 64 + d];
        const float e2 = sWt[8192 + k * 64 + d];
        const float h0 = sh[n0][k], h1 = sh[n0 + 1][k];
        wh0 += h0 * w;  wh1 += h1 * w;
        ei0 += h0 * e1; ei1 += h1 * e1;
        ej0 += h0 * e2; ej1 += h1 * e2;
    }
    const int na = nb + n0;
    g_Wh[na * D + d] = wh0;       g_Wh[(na + 1) * D + d] = wh1;
    g_ei[na * D + d] = ei0;       g_ei[(na + 1) * D + d] = ei1;
    g_ej[na * D + d] = ej0;       g_ej[(na + 1) * D + d] = ej1;
    swh[n0][d] = wh0;             swh[n0 + 1][d] = wh1;
    __syncthreads();

    #pragma unroll
    for (int x = t; x < 2048; x += 256)
        ((float4*)sWt)[x] = ((const float4*)attn_w1)[x];
    __syncthreads();

    float qi0 = attn_b1[d], qi1 = qi0;
    float kj0 = 0.f, kj1 = 0.f;
    #pragma unroll 8
    for (int k = 0; k < D; ++k) {
        const float a1 = sWt[k * 64 + d];
        const float a2 = sWt[4096 + k * 64 + d];
        const float w0 = swh[n0][k], w1 = swh[n0 + 1][k];
        qi0 += w0 * a1; qi1 += w1 * a1;
        kj0 += w0 * a2; kj1 += w1 * a2;
    }
    g_qi[na * D + d] = qi0;       g_qi[(na + 1) * D + d] = qi1;
    g_kj[na * D + d] = kj0;       g_kj[(na + 1) * D + d] = kj1;
}

// ================================================================
// Kernel 2: attention scores via mma.sync bf16 (m16n8k16), d-split.
//   8 warps = 4 pairs x 2 d-halves. Pair p: j in [16p,16p+16);
//   warp half owns 32 d columns -> Bf 16 regs, acc 16 regs (no spills).
//   B register-resident; one __syncthreads per i (double-buffered sRed).
//   3 blocks/SM.
// ================================================================
#define JT 64
#define CHUNK_I 16

__global__ void __launch_bounds__(256, 3) escore_hmma_kernel(
    const float* __restrict__ attn_w1, const float* __restrict__ attn_w2,
    const float* __restrict__ attn_b2, const int* __restrict__ adj)
{
    __shared__ float sEj[JT][68];
    __shared__ float sKj[JT][68];
    __shared__ float sAe[64][68];
    __shared__ float sEi[CHUNK_I][64];
    __shared__ float sQi[CHUNK_I][64];
    __shared__ float sW2[64];
    __shared__ float sRed[2][4][2][16];

    const int tid  = threadIdx.x;
    const int wid  = tid >> 5;
    const int lane = tid & 31;
    const int gid  = lane >> 2;     // 0..7
    const int tig  = lane & 3;      // 0..3
    const int wpair = wid >> 1;     // 0..3 -> j group
    const int dhalf = wid & 1;      // 0..1 -> d half
    const int j0   = blockIdx.x * JT;
    const int iBase = blockIdx.y * CHUNK_I;

    // ---- stage block tiles ----
    for (int x = tid; x < JT * 64; x += 256) {
        const int j = x >> 6, k = x & 63;
        sEj[j][k] = g_ej[(j0 + j) * D + k];
        sKj[j][k] = g_kj[(j0 + j) * D + k];
    }
    for (int x = tid; x < 64 * 64; x += 256) {
        const int k = x >> 6, d = x & 63;
        sAe[k][d] = attn_w1[(128 + k) * D + d];   // A_e
    }
    for (int x = tid; x < CHUNK_I * 64; x += 256) {
        const int ii = x >> 6, d = x & 63;
        sEi[ii][d] = g_ei[(iBase + ii) * D + d];
        sQi[ii][d] = g_qi[(iBase + ii) * D + d];
    }
    if (tid < 64) sW2[tid] = attn_w2[tid];
    __syncthreads();

    // ---- B fragments (bf16, register-resident): this warp's 32 d cols ----
    const int d0 = dhalf * 32;
    uint32_t Bf[4][4][2];
    #pragma unroll
    for (int s = 0; s < 4; ++s)
        #pragma unroll
        for (int nt = 0; nt < 4; ++nt) {
            const int dd = d0 + 8 * nt + gid;
            const int kb = 16 * s + 2 * tig;
            Bf[s][nt][0] = pack_bf16x2(sAe[kb][dd],     sAe[kb + 1][dd]);
            Bf[s][nt][1] = pack_bf16x2(sAe[kb + 8][dd], sAe[kb + 9][dd]);
        }

    const int jw = wpair * 16;
    const float b2 = attn_b2[0];

    #pragma unroll 1
    for (int ii = 0; ii < CHUNK_I; ++ii) {
        const int i = iBase + ii;

        // acc init = qi + kj (this warp's 32 d)
        float acc[4][4];
        #pragma unroll
        for (int nt = 0; nt < 4; ++nt) {
            const int off = d0 + 8 * nt + 2 * tig;
            const float2 q  = *(const float2*)&sQi[ii][off];
            const float2 k0 = *(const float2*)&sKj[jw + gid][off];
            const float2 k1 = *(const float2*)&sKj[jw + gid + 8][off];
            acc[nt][0] = q.x + k0.x; acc[nt][1] = q.y + k0.y;
            acc[nt][2] = q.x + k1.x; acc[nt][3] = q.y + k1.y;
        }

        // k loop: 4 steps of k16
        #pragma unroll
        for (int s = 0; s < 4; ++s) {
            const int kb = 16 * s + 2 * tig;
            const float2 eia = *(const float2*)&sEi[ii][kb];
            const float2 eib = *(const float2*)&sEi[ii][kb + 8];
            const float2 ja0 = *(const float2*)&sEj[jw + gid][kb];
            const float2 jb0 = *(const float2*)&sEj[jw + gid][kb + 8];
            const float2 ja1 = *(const float2*)&sEj[jw + gid + 8][kb];
            const float2 jb1 = *(const float2*)&sEj[jw + gid + 8][kb + 8];

            const uint32_t a0 = pack_bf16x2(leaky(eia.x + ja0.x), leaky(eia.y + ja0.y));
            const uint32_t a1 = pack_bf16x2(leaky(eia.x + ja1.x), leaky(eia.y + ja1.y));
            const uint32_t a2 = pack_bf16x2(leaky(eib.x + jb0.x), leaky(eib.y + jb0.y));
            const uint32_t a3 = pack_bf16x2(leaky(eib.x + jb1.x), leaky(eib.y + jb1.y));

            #pragma unroll
            for (int nt = 0; nt < 4; ++nt)
                mma_bf16_16x8x16(acc[nt][0], acc[nt][1], acc[nt][2], acc[nt][3],
                                 a0, a1, a2, a3, Bf[s][nt][0], Bf[s][nt][1]);
        }

        // partial epilogue over this warp's 32 d: leaky + dot w2
        float er0 = 0.f, er1 = 0.f;
        #pragma unroll
        for (int nt = 0; nt < 4; ++nt) {
            const int off = d0 + 8 * nt + 2 * tig;
            const float w0 = sW2[off];
            const float w1 = sW2[off + 1];
            er0 = fmaf(leaky(acc[nt][0]), w0, er0);
            er0 = fmaf(leaky(acc[nt][1]), w1, er0);
            er1 = fmaf(leaky(acc[nt][2]), w0, er1);
            er1 = fmaf(leaky(acc[nt][3]), w1, er1);
        }
        er0 += __shfl_xor_sync(0xffffffffu, er0, 1);
        er0 += __shfl_xor_sync(0xffffffffu, er0, 2);
        er1 += __shfl_xor_sync(0xffffffffu, er1, 1);
        er1 += __shfl_xor_sync(0xffffffffu, er1, 2);
        if (tig == 0) {
            sRed[ii & 1][wpair][dhalf][gid]     = er0;
            sRed[ii & 1][wpair][dhalf][gid + 8] = er1;
        }
        __syncthreads();

        // combine d-halves, mask, store (64 threads)
        if (tid < 64) {
            const int p = tid >> 4, jl = tid & 15;
            float e = sRed[ii & 1][p][0][jl] + sRed[ii & 1][p][1][jl] + b2;
            const int j = j0 + p * 16 + jl;
            if (adj[i * N_NODES + j] == 0) e = MASK_VAL_F;
            g_e[i * N_NODES + j] = e;
        }
    }
}

// ================================================================
// Kernel 3: softmax + aggregate + LN; 8 rows per block (Wh reuse, 1 wave).
// ================================================================
#define R8 8
__global__ void __launch_bounds__(256) softmax_ln_kernel(
    const float* __restrict__ h, const float* __restrict__ ln_g,
    const float* __restrict__ ln_b, float* __restrict__ out)
{
    __shared__ float sp[R8][N_NODES];       // 32KB
    __shared__ float red[R8][8];
    __shared__ float part[R8][4][64];       // 8KB
    __shared__ float shp[R8][64];
    __shared__ float sInv[R8], sMu[R8], sVar[R8];

    const int i0 = blockIdx.x * R8;
    const int t = threadIdx.x;
    const int lane = t & 31, wid = t >> 5;

    float m[R8];
    #pragma unroll
    for (int r = 0; r < R8; ++r) m[r] = -3.4e38f;
    for (int j = t; j < N_NODES; j += 256) {
        #pragma unroll
        for (int r = 0; r < R8; ++r) {
            const float v = g_e[(i0 + r) * N_NODES + j];
            sp[r][j] = v;
            m[r] = fmaxf(m[r], v);
        }
    }
    #pragma unroll
    for (int r = 0; r < R8; ++r) {
        m[r] = warpReduceMax(m[r]);
        if (lane == 0) red[r][wid] = m[r];
    }
    __syncthreads();
    if (t < R8) {
        float mm = red[t][0];
        #pragma unroll
        for (int w = 1; w < 8; ++w) mm = fmaxf(mm, red[t][w]);
        sInv[t] = mm;
    }
    __syncthreads();
    #pragma unroll
    for (int r = 0; r < R8; ++r) m[r] = sInv[r];
    __syncthreads();

    float s[R8];
    #pragma unroll
    for (int r = 0; r < R8; ++r) s[r] = 0.f;
    for (int j = t; j < N_NODES; j += 256) {
        #pragma unroll
        for (int r = 0; r < R8; ++r) {
            const float p = __expf(sp[r][j] - m[r]);
            sp[r][j] = p;
            s[r] += p;
        }
    }
    #pragma unroll
    for (int r = 0; r < R8; ++r) {
        s[r] = warpReduceSum(s[r]);
        if (lane == 0) red[r][wid] = s[r];
    }
    __syncthreads();
    if (t < R8) {
        float ss = 0.f;
        #pragma unroll
        for (int w = 0; w < 8; ++w) ss += red[t][w];
        sInv[t] = 1.0f / ss;
    }
    __syncthreads();

    const int g = t >> 6, d = t & 63;
    const int jb = g * 256;
    float a[R8];
    #pragma unroll
    for (int r = 0; r < R8; ++r) a[r] = 0.f;
    #pragma unroll 2
    for (int jj = 0; jj < 256; jj += 4) {
        const float w0 = g_Wh[(jb + jj + 0) * D + d];
        const float w1 = g_Wh[(jb + jj + 1) * D + d];
        const float w2 = g_Wh[(jb + jj + 2) * D + d];
        const float w3 = g_Wh[(jb + jj + 3) * D + d];
        #pragma unroll
        for (int r = 0; r < R8; ++r) {
            const float4 p = *(const float4*)&sp[r][jb + jj];
            a[r] += p.x * w0 + p.y * w1 + p.z * w2 + p.w * w3;
        }
    }
    #pragma unroll
    for (int r = 0; r < R8; ++r) part[r][g][d] = a[r];
    __syncthreads();

    #pragma unroll
    for (int it = 0; it < 2; ++it) {
        const int idx = t + it * 256;
        const int r = idx >> 6, dd = idx & 63;
        const float hp = (part[r][0][dd] + part[r][1][dd] + part[r][2][dd] + part[r][3][dd])
                         * sInv[r] + h[(i0 + r) * D + dd];
        shp[r][dd] = hp;
    }
    __syncthreads();

    {
        const int r = wid;
        float v = shp[r][lane] + shp[r][lane + 32];
        v = warpReduceSum(v);
        if (lane == 0) sMu[r] = v * (1.0f / 64.0f);
    }
    __syncthreads();
    {
        const int r = wid;
        const float mu = sMu[r];
        const float d0 = shp[r][lane] - mu, d1 = shp[r][lane + 32] - mu;
        float v = d0 * d0 + d1 * d1;
        v = warpReduceSum(v);
        if (lane == 0) sVar[r] = v * (1.0f / 64.0f);
    }
    __syncthreads();

    #pragma unroll
    for (int it = 0; it < 2; ++it) {
        const int idx = t + it * 256;
        const int r = idx >> 6, dd = idx & 63;
        const float mu = sMu[r];
        const float rstd = rsqrtf(sVar[r] + LN_EPS_F);
        out[(i0 + r) * D + dd] = (shp[r][dd] - mu) * rstd * ln_g[dd] + ln_b[dd];
    }
}

// ================================================================
extern "C" void kernel_launch(void* const* d_in, const int* in_sizes, int n_in,
                              void* d_out, int out_size) {
    const float* h        = (const float*)d_in[0];
    const int*   adj      = (const int*)  d_in[1];
    const float* W        = (const float*)d_in[2];
    const float* attn_w1  = (const float*)d_in[3];
    const float* attn_b1  = (const float*)d_in[4];
    const float* attn_w2  = (const float*)d_in[5];
    const float* attn_b2  = (const float*)d_in[6];
    const float* edge_w   = (const float*)d_in[7];
    const float* edge_b   = (const float*)d_in[8];
    const float* ln_g     = (const float*)d_in[9];
    const float* ln_b     = (const float*)d_in[10];
    float* out = (float*)d_out;

    prep_kernel<<<N_NODES / 8, 256>>>(h, W, attn_w1, attn_b1, edge_w, edge_b);

    dim3 grid(N_NODES / JT, N_NODES / CHUNK_I);
    escore_hmma_kernel<<<grid, 256>>>(attn_w1, attn_w2, attn_b2, adj);

    softmax_ln_kernel<<<N_NODES / R8, 256>>>(h, ln_g, ln_b, out);
}

// round 9
// speedup vs baseline: 1.3106x; 1.3106x over previous
#include <cuda_runtime.h>
#include <cstdint>

#define N_NODES 1024
#define D 64
#define ALPHA_F 0.2f
#define MASK_VAL_F -1000000000.0f
#define LN_EPS_F 1e-5f

// ---------------- scratch (no allocations allowed) ----------------
__device__ float g_Wh[N_NODES * D];
__device__ float g_ei[N_NODES * D];   // h @ E_i + edge_b (folded)
__device__ float g_ej[N_NODES * D];   // h @ E_j
__device__ float g_qi[N_NODES * D];   // Wh @ A_i + attn_b1 (folded)
__device__ float g_kj[N_NODES * D];   // Wh @ A_j
__device__ float g_e[N_NODES * N_NODES];

// ---------------- helpers ----------------
__device__ __forceinline__ float warpReduceMax(float v) {
    #pragma unroll
    for (int o = 16; o > 0; o >>= 1) v = fmaxf(v, __shfl_xor_sync(0xffffffffu, v, o));
    return v;
}
__device__ __forceinline__ float warpReduceSum(float v) {
    #pragma unroll
    for (int o = 16; o > 0; o >>= 1) v += __shfl_xor_sync(0xffffffffu, v, o);
    return v;
}
// pack {lo, hi} floats -> bf16x2 (element0 = lo)
__device__ __forceinline__ uint32_t pack_bf16x2(float lo, float hi) {
    uint32_t r;
    asm("cvt.rn.bf16x2.f32 %0, %1, %2;" : "=r"(r) : "f"(hi), "f"(lo));
    return r;
}
__device__ __forceinline__ void mma_bf16_16x8x16(
    float& c0, float& c1, float& c2, float& c3,
    uint32_t a0, uint32_t a1, uint32_t a2, uint32_t a3,
    uint32_t b0, uint32_t b1)
{
    asm volatile(
        "mma.sync.aligned.m16n8k16.row.col.f32.bf16.bf16.f32 "
        "{%0,%1,%2,%3}, {%4,%5,%6,%7}, {%8,%9}, {%0,%1,%2,%3};"
        : "+f"(c0), "+f"(c1), "+f"(c2), "+f"(c3)
        : "r"(a0), "r"(a1), "r"(a2), "r"(a3), "r"(b0), "r"(b1));
}
__device__ __forceinline__ float leaky(float s) { return fmaxf(s, ALPHA_F * s); }

// ================================================================
// Kernel 1: per-node projections. Weights staged in SMEM.
// 128 blocks x 8 nodes, 2 nodes/thread.  (measured 7.8us config)
// ================================================================
__global__ void __launch_bounds__(256) prep_kernel(
    const float* __restrict__ h, const float* __restrict__ W,
    const float* __restrict__ attn_w1, const float* __restrict__ attn_b1,
    const float* __restrict__ edge_w, const float* __restrict__ edge_b)
{
    __shared__ float sWt[12288];          // 48KB
    __shared__ float sh[8][64];
    __shared__ float swh[8][64];
    const int t = threadIdx.x;
    const int d = t & 63;
    const int n0 = (t >> 6) * 2;
    const int nb = blockIdx.x * 8;

    #pragma unroll
    for (int x = t; x < 1024; x += 256)
        ((float4*)sWt)[x] = ((const float4*)W)[x];
    #pragma unroll
    for (int x = t; x < 2048; x += 256)
        ((float4*)(sWt + 4096))[x] = ((const float4*)edge_w)[x];
    if (t < 128)
        ((float4*)sh)[t] = ((const float4*)(h + nb * D))[t];
    __syncthreads();

    float wh0 = 0.f, wh1 = 0.f;
    float ei0 = edge_b[d], ei1 = ei0;
    float ej0 = 0.f, ej1 = 0.f;
    #pragma unroll 8
    for (int k = 0; k < D; ++k) {
        const float w  = sWt[k * 64 + d];
        const float e1 = sWt[4096 + k * 64 + d];
        const float e2 = sWt[8192 + k * 64 + d];
        const float h0 = sh[n0][k], h1 = sh[n0 + 1][k];
        wh0 += h0 * w;  wh1 += h1 * w;
        ei0 += h0 * e1; ei1 += h1 * e1;
        ej0 += h0 * e2; ej1 += h1 * e2;
    }
    const int na = nb + n0;
    g_Wh[na * D + d] = wh0;       g_Wh[(na + 1) * D + d] = wh1;
    g_ei[na * D + d] = ei0;       g_ei[(na + 1) * D + d] = ei1;
    g_ej[na * D + d] = ej0;       g_ej[(na + 1) * D + d] = ej1;
    swh[n0][d] = wh0;             swh[n0 + 1][d] = wh1;
    __syncthreads();

    #pragma unroll
    for (int x = t; x < 2048; x += 256)
        ((float4*)sWt)[x] = ((const float4*)attn_w1)[x];
    __syncthreads();

    float qi0 = attn_b1[d], qi1 = qi0;
    float kj0 = 0.f, kj1 = 0.f;
    #pragma unroll 8
    for (int k = 0; k < D; ++k) {
        const float a1 = sWt[k * 64 + d];
        const float a2 = sWt[4096 + k * 64 + d];
        const float w0 = swh[n0][k], w1 = swh[n0 + 1][k];
        qi0 += w0 * a1; qi1 += w1 * a1;
        kj0 += w0 * a2; kj1 += w1 * a2;
    }
    g_qi[na * D + d] = qi0;       g_qi[(na + 1) * D + d] = qi1;
    g_kj[na * D + d] = kj0;       g_kj[(na + 1) * D + d] = kj1;
}

// ================================================================
// Kernel 2: attention scores via mma.sync bf16 (m16n8k16).
//   R5-proven structure: 8 warps x 16 j, full d=64 per warp,
//   B register-resident (64 regs). New: ej fragments hoisted out of
//   the i-loop (i-invariant, 32 regs); CHUNK_I = 32.
// ================================================================
#define CHUNK_I 32

__global__ void __launch_bounds__(256, 1) escore_hmma_kernel(
    const float* __restrict__ attn_w1, const float* __restrict__ attn_w2,
    const float* __restrict__ attn_b2, const int* __restrict__ adj)
{
    __shared__ float sEj[128][68];
    __shared__ float sKj[128][68];
    __shared__ float sAe[64][68];
    __shared__ float sEi[CHUNK_I][64];
    __shared__ float sQi[CHUNK_I][64];
    __shared__ float sW2[64];

    const int tid  = threadIdx.x;
    const int wid  = tid >> 5;
    const int lane = tid & 31;
    const int gid  = lane >> 2;     // 0..7
    const int tig  = lane & 3;      // 0..3
    const int j0   = blockIdx.x * 128;
    const int iBase = blockIdx.y * CHUNK_I;

    // ---- stage block tiles ----
    for (int x = tid; x < 128 * 64; x += 256) {
        const int j = x >> 6, k = x & 63;
        sEj[j][k] = g_ej[(j0 + j) * D + k];
        sKj[j][k] = g_kj[(j0 + j) * D + k];
    }
    for (int x = tid; x < 64 * 64; x += 256) {
        const int k = x >> 6, d = x & 63;
        sAe[k][d] = attn_w1[(128 + k) * D + d];   // A_e
    }
    for (int x = tid; x < CHUNK_I * 64; x += 256) {
        const int ii = x >> 6, d = x & 63;
        sEi[ii][d] = g_ei[(iBase + ii) * D + d];
        sQi[ii][d] = g_qi[(iBase + ii) * D + d];
    }
    if (tid < 64) sW2[tid] = attn_w2[tid];
    __syncthreads();

    // ---- B fragments (bf16, register-resident, whole kernel) ----
    uint32_t Bf[4][8][2];
    #pragma unroll
    for (int s = 0; s < 4; ++s)
        #pragma unroll
        for (int nt = 0; nt < 8; ++nt) {
            const int dd = 8 * nt + gid;
            const int kb = 16 * s + 2 * tig;
            Bf[s][nt][0] = pack_bf16x2(sAe[kb][dd],     sAe[kb + 1][dd]);
            Bf[s][nt][1] = pack_bf16x2(sAe[kb + 8][dd], sAe[kb + 9][dd]);
        }

    const int jw = wid * 16;
    const float b2 = attn_b2[0];

    // ---- hoist ej fragments (i-invariant): 16 float2 = 32 regs ----
    float2 eja0[4], ejb0[4], eja1[4], ejb1[4];
    #pragma unroll
    for (int s = 0; s < 4; ++s) {
        const int kb = 16 * s + 2 * tig;
        eja0[s] = *(const float2*)&sEj[jw + gid][kb];
        ejb0[s] = *(const float2*)&sEj[jw + gid][kb + 8];
        eja1[s] = *(const float2*)&sEj[jw + gid + 8][kb];
        ejb1[s] = *(const float2*)&sEj[jw + gid + 8][kb + 8];
    }

    #pragma unroll 1
    for (int ii = 0; ii < CHUNK_I; ++ii) {
        const int i = iBase + ii;

        // acc init = qi + kj
        float acc[8][4];
        #pragma unroll
        for (int nt = 0; nt < 8; ++nt) {
            const float2 q  = *(const float2*)&sQi[ii][8 * nt + 2 * tig];
            const float2 k0 = *(const float2*)&sKj[jw + gid][8 * nt + 2 * tig];
            const float2 k1 = *(const float2*)&sKj[jw + gid + 8][8 * nt + 2 * tig];
            acc[nt][0] = q.x + k0.x; acc[nt][1] = q.y + k0.y;
            acc[nt][2] = q.x + k1.x; acc[nt][3] = q.y + k1.y;
        }

        // k loop: 4 steps of k16 (ej from registers)
        #pragma unroll
        for (int s = 0; s < 4; ++s) {
            const int kb = 16 * s + 2 * tig;
            const float2 eia = *(const float2*)&sEi[ii][kb];
            const float2 eib = *(const float2*)&sEi[ii][kb + 8];

            const uint32_t a0 = pack_bf16x2(leaky(eia.x + eja0[s].x), leaky(eia.y + eja0[s].y));
            const uint32_t a1 = pack_bf16x2(leaky(eia.x + eja1[s].x), leaky(eia.y + eja1[s].y));
            const uint32_t a2 = pack_bf16x2(leaky(eib.x + ejb0[s].x), leaky(eib.y + ejb0[s].y));
            const uint32_t a3 = pack_bf16x2(leaky(eib.x + ejb1[s].x), leaky(eib.y + ejb1[s].y));

            #pragma unroll
            for (int nt = 0; nt < 8; ++nt)
                mma_bf16_16x8x16(acc[nt][0], acc[nt][1], acc[nt][2], acc[nt][3],
                                 a0, a1, a2, a3, Bf[s][nt][0], Bf[s][nt][1]);
        }

        // epilogue: leaky + dot w2, quad-reduce, mask, store
        float er0 = 0.f, er1 = 0.f;
        #pragma unroll
        for (int nt = 0; nt < 8; ++nt) {
            const float w0 = sW2[8 * nt + 2 * tig];
            const float w1 = sW2[8 * nt + 2 * tig + 1];
            er0 = fmaf(leaky(acc[nt][0]), w0, er0);
            er0 = fmaf(leaky(acc[nt][1]), w1, er0);
            er1 = fmaf(leaky(acc[nt][2]), w0, er1);
            er1 = fmaf(leaky(acc[nt][3]), w1, er1);
        }
        er0 += __shfl_xor_sync(0xffffffffu, er0, 1);
        er0 += __shfl_xor_sync(0xffffffffu, er0, 2);
        er1 += __shfl_xor_sync(0xffffffffu, er1, 1);
        er1 += __shfl_xor_sync(0xffffffffu, er1, 2);
        if (tig == 0) {
            const int jA = j0 + jw + gid;
            const int jB = jA + 8;
            float eA = er0 + b2, eB = er1 + b2;
            if (adj[i * N_NODES + jA] == 0) eA = MASK_VAL_F;
            if (adj[i * N_NODES + jB] == 0) eB = MASK_VAL_F;
            g_e[i * N_NODES + jA] = eA;
            g_e[i * N_NODES + jB] = eB;
        }
    }
}

// ================================================================
// Kernel 3: softmax + aggregate + LN; 8 rows per block (Wh reuse, 1 wave).
// ================================================================
#define R8 8
__global__ void __launch_bounds__(256) softmax_ln_kernel(
    const float* __restrict__ h, const float* __restrict__ ln_g,
    const float* __restrict__ ln_b, float* __restrict__ out)
{
    __shared__ float sp[R8][N_NODES];       // 32KB
    __shared__ float red[R8][8];
    __shared__ float part[R8][4][64];       // 8KB
    __shared__ float shp[R8][64];
    __shared__ float sInv[R8], sMu[R8], sVar[R8];

    const int i0 = blockIdx.x * R8;
    const int t = threadIdx.x;
    const int lane = t & 31, wid = t >> 5;

    float m[R8];
    #pragma unroll
    for (int r = 0; r < R8; ++r) m[r] = -3.4e38f;
    for (int j = t; j < N_NODES; j += 256) {
        #pragma unroll
        for (int r = 0; r < R8; ++r) {
            const float v = g_e[(i0 + r) * N_NODES + j];
            sp[r][j] = v;
            m[r] = fmaxf(m[r], v);
        }
    }
    #pragma unroll
    for (int r = 0; r < R8; ++r) {
        m[r] = warpReduceMax(m[r]);
        if (lane == 0) red[r][wid] = m[r];
    }
    __syncthreads();
    if (t < R8) {
        float mm = red[t][0];
        #pragma unroll
        for (int w = 1; w < 8; ++w) mm = fmaxf(mm, red[t][w]);
        sInv[t] = mm;
    }
    __syncthreads();
    #pragma unroll
    for (int r = 0; r < R8; ++r) m[r] = sInv[r];
    __syncthreads();

    float s[R8];
    #pragma unroll
    for (int r = 0; r < R8; ++r) s[r] = 0.f;
    for (int j = t; j < N_NODES; j += 256) {
        #pragma unroll
        for (int r = 0; r < R8; ++r) {
            const float p = __expf(sp[r][j] - m[r]);
            sp[r][j] = p;
            s[r] += p;
        }
    }
    #pragma unroll
    for (int r = 0; r < R8; ++r) {
        s[r] = warpReduceSum(s[r]);
        if (lane == 0) red[r][wid] = s[r];
    }
    __syncthreads();
    if (t < R8) {
        float ss = 0.f;
        #pragma unroll
        for (int w = 0; w < 8; ++w) ss += red[t][w];
        sInv[t] = 1.0f / ss;
    }
    __syncthreads();

    const int g = t >> 6, d = t & 63;
    const int jb = g * 256;
    float a[R8];
    #pragma unroll
    for (int r = 0; r < R8; ++r) a[r] = 0.f;
    #pragma unroll 2
    for (int jj = 0; jj < 256; jj += 4) {
        const float w0 = g_Wh[(jb + jj + 0) * D + d];
        const float w1 = g_Wh[(jb + jj + 1) * D + d];
        const float w2 = g_Wh[(jb + jj + 2) * D + d];
        const float w3 = g_Wh[(jb + jj + 3) * D + d];
        #pragma unroll
        for (int r = 0; r < R8; ++r) {
            const float4 p = *(const float4*)&sp[r][jb + jj];
            a[r] += p.x * w0 + p.y * w1 + p.z * w2 + p.w * w3;
        }
    }
    #pragma unroll
    for (int r = 0; r < R8; ++r) part[r][g][d] = a[r];
    __syncthreads();

    #pragma unroll
    for (int it = 0; it < 2; ++it) {
        const int idx = t + it * 256;
        const int r = idx >> 6, dd = idx & 63;
        const float hp = (part[r][0][dd] + part[r][1][dd] + part[r][2][dd] + part[r][3][dd])
                         * sInv[r] + h[(i0 + r) * D + dd];
        shp[r][dd] = hp;
    }
    __syncthreads();

    {
        const int r = wid;
        float v = shp[r][lane] + shp[r][lane + 32];
        v = warpReduceSum(v);
        if (lane == 0) sMu[r] = v * (1.0f / 64.0f);
    }
    __syncthreads();
    {
        const int r = wid;
        const float mu = sMu[r];
        const float d0 = shp[r][lane] - mu, d1 = shp[r][lane + 32] - mu;
        float v = d0 * d0 + d1 * d1;
        v = warpReduceSum(v);
        if (lane == 0) sVar[r] = v * (1.0f / 64.0f);
    }
    __syncthreads();

    #pragma unroll
    for (int it = 0; it < 2; ++it) {
        const int idx = t + it * 256;
        const int r = idx >> 6, dd = idx & 63;
        const float mu = sMu[r];
        const float rstd = rsqrtf(sVar[r] + LN_EPS_F);
        out[(i0 + r) * D + dd] = (shp[r][dd] - mu) * rstd * ln_g[dd] + ln_b[dd];
    }
}

// ================================================================
extern "C" void kernel_launch(void* const* d_in, const int* in_sizes, int n_in,
                              void* d_out, int out_size) {
    const float* h        = (const float*)d_in[0];
    const int*   adj      = (const int*)  d_in[1];
    const float* W        = (const float*)d_in[2];
    const float* attn_w1  = (const float*)d_in[3];
    const float* attn_b1  = (const float*)d_in[4];
    const float* attn_w2  = (const float*)d_in[5];
    const float* attn_b2  = (const float*)d_in[6];
    const float* edge_w   = (const float*)d_in[7];
    const float* edge_b   = (const float*)d_in[8];
    const float* ln_g     = (const float*)d_in[9];
    const float* ln_b     = (const float*)d_in[10];
    float* out = (float*)d_out;

    prep_kernel<<<N_NODES / 8, 256>>>(h, W, attn_w1, attn_b1, edge_w, edge_b);

    dim3 grid(N_NODES / 128, N_NODES / CHUNK_I);
    escore_hmma_kernel<<<grid, 256>>>(attn_w1, attn_w2, attn_b2, adj);

    softmax_ln_kernel<<<N_NODES / R8, 256>>>(h, ln_g, ln_b, out);
}